// round 6
// baseline (speedup 1.0000x reference)
#include <cuda_runtime.h>
#include <cuda_bf16.h>

#define BB 4
#define SS 512
#define EE 512
#define UU 256
#define KSPLIT 4

// Scratch (__device__ globals, allocation-free rule)
__device__ float g_K[BB * SS * UU];            // key_pre + b1
__device__ float g_Q[BB * SS * UU];            // qry_pre
__device__ float g_S[BB * SS * SS];            // softmax probs
__device__ float g_part[KSPLIT * 2048 * 512];  // 16MB split-K partials (shared)

typedef unsigned long long u64;

__device__ __forceinline__ u64 pack2(float x, float y) {
    u64 r; asm("mov.b64 %0,{%1,%2};" : "=l"(r) : "f"(x), "f"(y)); return r;
}
__device__ __forceinline__ u64 fma2(u64 a, u64 b, u64 c) {
    u64 d; asm("fma.rn.f32x2 %0,%1,%2,%3;" : "=l"(d) : "l"(a), "l"(b), "l"(c)); return d;
}
__device__ __forceinline__ float2 unpack2(u64 v) {
    float2 f; asm("mov.b64 {%0,%1},%2;" : "=f"(f.x), "=f"(f.y) : "l"(v)); return f;
}
__device__ __forceinline__ float tanh_ap(float x) {
    float y; asm("tanh.approx.f32 %0,%1;" : "=f"(y) : "f"(x)); return y;
}
__device__ __forceinline__ float ex2_ap(float x) {
    float y; asm("ex2.approx.f32 %0,%1;" : "=f"(y) : "f"(x)); return y;
}
__device__ __forceinline__ void cp16(void* dst, const void* src) {
    unsigned d = (unsigned)__cvta_generic_to_shared(dst);
    asm volatile("cp.async.ca.shared.global [%0],[%1],16;" :: "r"(d), "l"(src) : "memory");
}

// ---------------------------------------------------------------------------
// 64x64 tile x K=128 chunk SGEMM. 128 threads, 4(M)x8(N) micro, N-PACKED
// FFMA2 accumulators: B pairs natural from smem, A scalars duplicated via
// ALU movs (idle pipe). LDS per warp-kk (dedup): A 1 wf + B 2 wf = 3 cyc vs
// 32 fma cyc -> fma-bound. Double-buffered smem, one sync per K-step.
// ~70 regs -> with 1024-CTA grids the whole stage is one resident wave.
// ---------------------------------------------------------------------------
__device__ __forceinline__ void sgemm_64x64_np(
    const float* __restrict__ A, const float* __restrict__ B,
    float* __restrict__ P, int lda, int ldb, int ldp,
    int row0, int col0)
{
    __shared__ __align__(16) float As[2][8][64];   // [buf][k][m]
    __shared__ __align__(16) float Bs[2][8][64];   // [buf][k][n]

    const int tid = threadIdx.x;
    const int tx = tid & 7;           // N group: cols tx*8 .. tx*8+7
    const int ty = tid >> 3;          // M group: rows ty*4 .. ty*4+3
    const int ar = tid >> 1;          // A load: m row 0..63
    const int ak = (tid & 1) * 4;     // A load: k base 0/4
    const int br = tid >> 4;          // B load: k row 0..7
    const int bc = (tid & 15) * 4;    // B load: n col 0..60

    const float* Ap = A + (size_t)(row0 + ar) * lda + ak;
    const float* Bp = B + (size_t)br * ldb + col0 + bc;

    float4 pa = *(const float4*)Ap;
    float4 pb = *(const float4*)Bp;

    u64 acc[4][4];
#pragma unroll
    for (int m = 0; m < 4; m++)
#pragma unroll
        for (int j = 0; j < 4; j++) acc[m][j] = 0ull;

    // stage 0
    As[0][ak + 0][ar] = pa.x;
    As[0][ak + 1][ar] = pa.y;
    As[0][ak + 2][ar] = pa.z;
    As[0][ak + 3][ar] = pa.w;
    *(float4*)&Bs[0][br][bc] = pb;
    __syncthreads();

#pragma unroll 2
    for (int it = 0; it < 16; it++) {
        const int buf = it & 1;
        if (it < 15) {
            pa = *(const float4*)(Ap + (it + 1) * 8);
            pb = *(const float4*)(Bp + (size_t)(it + 1) * 8 * ldb);
        }
#pragma unroll
        for (int kk = 0; kk < 8; kk++) {
            const float4 a = *(const float4*)&As[buf][kk][ty * 4];
            const ulonglong2 b01 = *(const ulonglong2*)&Bs[buf][kk][tx * 8];
            const ulonglong2 b23 = *(const ulonglong2*)&Bs[buf][kk][tx * 8 + 4];
            const u64 a0 = pack2(a.x, a.x);
            const u64 a1 = pack2(a.y, a.y);
            const u64 a2 = pack2(a.z, a.z);
            const u64 a3 = pack2(a.w, a.w);
            acc[0][0] = fma2(a0, b01.x, acc[0][0]);
            acc[0][1] = fma2(a0, b01.y, acc[0][1]);
            acc[0][2] = fma2(a0, b23.x, acc[0][2]);
            acc[0][3] = fma2(a0, b23.y, acc[0][3]);
            acc[1][0] = fma2(a1, b01.x, acc[1][0]);
            acc[1][1] = fma2(a1, b01.y, acc[1][1]);
            acc[1][2] = fma2(a1, b23.x, acc[1][2]);
            acc[1][3] = fma2(a1, b23.y, acc[1][3]);
            acc[2][0] = fma2(a2, b01.x, acc[2][0]);
            acc[2][1] = fma2(a2, b01.y, acc[2][1]);
            acc[2][2] = fma2(a2, b23.x, acc[2][2]);
            acc[2][3] = fma2(a2, b23.y, acc[2][3]);
            acc[3][0] = fma2(a3, b01.x, acc[3][0]);
            acc[3][1] = fma2(a3, b01.y, acc[3][1]);
            acc[3][2] = fma2(a3, b23.x, acc[3][2]);
            acc[3][3] = fma2(a3, b23.y, acc[3][3]);
        }
        if (it < 15) {
            const int nb = buf ^ 1;
            As[nb][ak + 0][ar] = pa.x;
            As[nb][ak + 1][ar] = pa.y;
            As[nb][ak + 2][ar] = pa.z;
            As[nb][ak + 3][ar] = pa.w;
            *(float4*)&Bs[nb][br][bc] = pb;
            __syncthreads();
        }
    }

    // epilogue: N-packed -> contiguous float4 stores
    const int ocol = col0 + tx * 8;
#pragma unroll
    for (int m = 0; m < 4; m++) {
        const float2 u0 = unpack2(acc[m][0]);
        const float2 u1 = unpack2(acc[m][1]);
        const float2 u2 = unpack2(acc[m][2]);
        const float2 u3 = unpack2(acc[m][3]);
        float* rp = P + (size_t)(row0 + ty * 4 + m) * ldp + ocol;
        *(float4*)rp       = make_float4(u0.x, u0.y, u1.x, u1.y);
        *(float4*)(rp + 4) = make_float4(u2.x, u2.y, u3.x, u3.y);
    }
}

// Stage 1a: split-K partials for K = h1@w1 (which=0) and Q = h2@w2 (which=1).
// grid (4, 32, 8 = which*4+ks), block 128 -> 1024 CTAs (one wave).
__global__ void __launch_bounds__(128)
qk_gemm_split(const float* __restrict__ h1, const float* __restrict__ h2,
              const float* __restrict__ w)
{
    const int which = blockIdx.z >> 2;
    const int ks    = blockIdx.z & 3;
    const int k0    = ks * 128;
    const float* A  = (which ? h2 : h1) + k0;
    const float* Bm = w + (size_t)which * EE * UU + (size_t)k0 * UU;
    float* P = g_part + (size_t)(ks * 2 + which) * 2048 * 256;
    sgemm_64x64_np(A, Bm, P, EE, UU, 256, blockIdx.y * 64, blockIdx.x * 64);
}

// Stage 1b: reduce partials -> g_K (+b1), g_Q. grid 1024, block 256.
__global__ void __launch_bounds__(256)
qk_reduce(const float* __restrict__ b1)
{
    const int t = blockIdx.x * 256 + threadIdx.x;
    const int which = t >> 17;
    const int i4 = t & 131071;
    const float4* p = (const float4*)g_part + (size_t)which * 131072 + i4;
    float4 s0 = p[0];
    float4 s1 = p[262144];
    float4 s2 = p[524288];
    float4 s3 = p[786432];
    float4 o = make_float4((s0.x + s1.x) + (s2.x + s3.x),
                           (s0.y + s1.y) + (s2.y + s3.y),
                           (s0.z + s1.z) + (s2.z + s3.z),
                           (s0.w + s1.w) + (s2.w + s3.w));
    if (which == 0) {
        const float4 bv = ((const float4*)b1)[i4 & 63];
        o.x += bv.x; o.y += bv.y; o.z += bv.z; o.w += bv.w;
        ((float4*)g_K)[i4] = o;
    } else {
        ((float4*)g_Q)[i4] = o;
    }
}

// Stage 3a: split-K partials for out[b] = P[b] @ h1[b].
// grid (8, 8, 16 = b*4+ks), block 128 -> 1024 CTAs (one wave).
__global__ void __launch_bounds__(128)
pv_gemm_split(const float* __restrict__ h1)
{
    const int b  = blockIdx.z >> 2;
    const int ks = blockIdx.z & 3;
    const int k0 = ks * 128;
    const float* A  = g_S + (size_t)b * SS * SS + k0;
    const float* Bm = h1  + (size_t)b * SS * EE + (size_t)k0 * EE;
    float* P = g_part + (size_t)ks * 2048 * 512 + (size_t)b * 512 * 512;
    sgemm_64x64_np(A, Bm, P, SS, EE, 512, blockIdx.y * 64, blockIdx.x * 64);
}

// Stage 3b: reduce partials -> out. grid 1024, block 256.
__global__ void __launch_bounds__(256)
pv_reduce(float* __restrict__ out)
{
    const int i4 = blockIdx.x * 256 + threadIdx.x;
    const float4* p = (const float4*)g_part + i4;
    float4 s0 = p[0];
    float4 s1 = p[262144];
    float4 s2 = p[524288];
    float4 s3 = p[786432];
    ((float4*)out)[i4] = make_float4((s0.x + s1.x) + (s2.x + s3.x),
                                     (s0.y + s1.y) + (s2.y + s3.y),
                                     (s0.z + s1.z) + (s2.z + s3.z),
                                     (s0.w + s1.w) + (s2.w + s3.w));
}

// ---------------------------------------------------------------------------
// Stage 2: fused scores + softmax, register-resident (at MUFU floor).
// grid (64, 4), block 256.
// ---------------------------------------------------------------------------
__global__ void __launch_bounds__(256)
scores_softmax(const float* __restrict__ v)
{
    __shared__ __align__(16) float4 qs[8][64];
    __shared__ __align__(16) float4 vs[64];
    __shared__ __align__(16) float4 ks[2][32][33];

    const int it = blockIdx.x;
    const int b  = blockIdx.y;
    const int tid = threadIdx.x;
    const int w  = tid >> 5;
    const int jl = tid & 31;

    const float4* Q4 = (const float4*)g_Q + (size_t)(b * SS + it * 8) * 64;
    const float4* K4 = (const float4*)g_K + (size_t)(b * SS) * 64;

    ((float4*)qs)[tid]       = Q4[tid];
    ((float4*)qs)[tid + 256] = Q4[tid + 256];
    if (tid < 64) vs[tid] = ((const float4*)v)[tid];

    const int lc = tid & 31;
    const int lr = (tid >> 5) * 4;

#pragma unroll
    for (int i = 0; i < 4; i++)
        cp16(&ks[0][lr + i][lc], K4 + (size_t)(lr + i) * 64 + lc);
    asm volatile("cp.async.commit_group;");
#pragma unroll
    for (int i = 0; i < 4; i++)
        cp16(&ks[1][lr + i][lc], K4 + (size_t)(32 + lr + i) * 64 + lc);
    asm volatile("cp.async.commit_group;");

    float acc[16];
#pragma unroll
    for (int i = 0; i < 16; i++) acc[i] = 0.f;

#pragma unroll 1
    for (int s = 0; s < 32; s++) {
        if (s < 31) { asm volatile("cp.async.wait_group 1;"); }
        else        { asm volatile("cp.async.wait_group 0;"); }
        __syncthreads();

        const int uc = s >> 4, jc = s & 15;
        const float4* kp = &ks[s & 1][jl][0];
        const float4* qp = &qs[w][uc * 32];
        const float4* vp = &vs[uc * 32];
        float ax = 0.f, ay = 0.f, az = 0.f, aw = 0.f;
#pragma unroll
        for (int cc = 0; cc < 32; cc++) {
            const float4 kv = kp[cc];
            const float4 qv = qp[cc];
            const float4 vv = vp[cc];
            ax += vv.x * tanh_ap(qv.x + kv.x);
            ay += vv.y * tanh_ap(qv.y + kv.y);
            az += vv.z * tanh_ap(qv.z + kv.z);
            aw += vv.w * tanh_ap(qv.w + kv.w);
        }
        acc[jc] += (ax + ay) + (az + aw);
        __syncthreads();

        if (s < 30) {
            const int s2 = s + 2;
            const int jc2 = s2 & 15, uc2 = s2 >> 4;
#pragma unroll
            for (int i = 0; i < 4; i++)
                cp16(&ks[s & 1][lr + i][lc],
                     K4 + (size_t)(jc2 * 32 + lr + i) * 64 + uc2 * 32 + lc);
            asm volatile("cp.async.commit_group;");
        }
    }

    float m = acc[0];
#pragma unroll
    for (int i = 1; i < 16; i++) m = fmaxf(m, acc[i]);
#pragma unroll
    for (int o = 16; o > 0; o >>= 1)
        m = fmaxf(m, __shfl_xor_sync(0xffffffffu, m, o));

    const float L2E = 1.4426950408889634f;
    float sum = 0.f;
#pragma unroll
    for (int i = 0; i < 16; i++) {
        acc[i] = ex2_ap((acc[i] - m) * L2E);
        sum += acc[i];
    }
#pragma unroll
    for (int o = 16; o > 0; o >>= 1)
        sum += __shfl_xor_sync(0xffffffffu, sum, o);
    const float inv = 1.0f / sum;

    float* prow = g_S + (size_t)(b * SS + it * 8 + w) * SS + jl;
#pragma unroll
    for (int jc = 0; jc < 16; jc++)
        prow[jc * 32] = acc[jc] * inv;
}

extern "C" void kernel_launch(void* const* d_in, const int* in_sizes, int n_in,
                              void* d_out, int out_size)
{
    const float* h1 = (const float*)d_in[0];
    const float* h2 = (const float*)d_in[1];
    const float* w  = (const float*)d_in[2];
    const float* b1 = (const float*)d_in[3];
    const float* v  = (const float*)d_in[4];
    // b2 (d_in[5]) unused: softmax is shift-invariant.
    float* out = (float*)d_out;

    dim3 gA(UU / 64, (BB * SS) / 64, 2 * KSPLIT);   // (4, 32, 8) = 1024 CTAs
    qk_gemm_split<<<gA, 128>>>(h1, h2, w);
    qk_reduce<<<1024, 256>>>(b1);

    dim3 gB(SS / 8, BB);                            // (64, 4) = 256 CTAs
    scores_softmax<<<gB, 256>>>(v);

    dim3 gD(EE / 64, SS / 64, BB * KSPLIT);         // (8, 8, 16) = 1024 CTAs
    pv_gemm_split<<<gD, 128>>>(h1);
    pv_reduce<<<1024, 256>>>(out);
}

// round 8
// speedup vs baseline: 1.2301x; 1.2301x over previous
#include <cuda_runtime.h>
#include <cuda_bf16.h>

#define BB 4
#define SS 512
#define EE 512
#define UU 256
#define KSPLIT 4

// Scratch (__device__ globals, allocation-free rule)
__device__ float g_K[BB * SS * UU];            // key_pre + b1
__device__ float g_Q[BB * SS * UU];            // qry_pre
__device__ float g_S[BB * SS * SS];            // scores -> probs
__device__ float g_part[KSPLIT * 2048 * 512];  // 16MB split-K partials (shared)

typedef unsigned long long u64;

__device__ __forceinline__ u64 pack2(float x, float y) {
    u64 r; asm("mov.b64 %0,{%1,%2};" : "=l"(r) : "f"(x), "f"(y)); return r;
}
__device__ __forceinline__ u64 fma2(u64 a, u64 b, u64 c) {
    u64 d; asm("fma.rn.f32x2 %0,%1,%2,%3;" : "=l"(d) : "l"(a), "l"(b), "l"(c)); return d;
}
__device__ __forceinline__ float2 unpack2(u64 v) {
    float2 f; asm("mov.b64 {%0,%1},%2;" : "=f"(f.x), "=f"(f.y) : "l"(v)); return f;
}
__device__ __forceinline__ float tanh_ap(float x) {
    float y; asm("tanh.approx.f32 %0,%1;" : "=f"(y) : "f"(x)); return y;
}
__device__ __forceinline__ float ex2_ap(float x) {
    float y; asm("ex2.approx.f32 %0,%1;" : "=f"(y) : "f"(x)); return y;
}

// ---------------------------------------------------------------------------
// 64(M) x 128(N) tile x K=128 chunk SGEMM (measured best: 35.5us/stage).
// 128 threads, 8x8 micro, FFMA2 with M-packed accumulators. BK=8,
// register-prefetch pipeline.
// ---------------------------------------------------------------------------
__device__ __forceinline__ void sgemm_64x128_k128(
    const float* __restrict__ A, const float* __restrict__ B,
    float* __restrict__ P, int lda, int ldb, int ldp,
    int row0, int col0)
{
    __shared__ __align__(16) float As[8][64];    // [k][m]
    __shared__ __align__(16) float Bs[8][128];   // [k][n]

    const int tid = threadIdx.x;
    const int tx = tid & 15;          // N micro group (8 cols)
    const int ty = tid >> 4;          // M micro group (8 rows)
    const int ar = tid >> 1;          // A load: m row 0..63
    const int ak = (tid & 1) * 4;     // A load: k base 0/4
    const int br = tid >> 4;          // B load: k row 0..7
    const int bc = (tid & 15) * 8;    // B load: n col 0..120

    const float* Ap = A + (size_t)(row0 + ar) * lda + ak;
    const float* Bp = B + (size_t)br * ldb + col0 + bc;

    float4 pa  = *(const float4*)Ap;
    float4 pb0 = *(const float4*)Bp;
    float4 pb1 = *(const float4*)(Bp + 4);

    u64 acc[4][8];
#pragma unroll
    for (int p = 0; p < 4; p++)
#pragma unroll
        for (int j = 0; j < 8; j++) acc[p][j] = 0ull;

#pragma unroll 1
    for (int k0 = 0; k0 < 128; k0 += 8) {
        As[ak + 0][ar] = pa.x;
        As[ak + 1][ar] = pa.y;
        As[ak + 2][ar] = pa.z;
        As[ak + 3][ar] = pa.w;
        *(float4*)&Bs[br][bc]     = pb0;
        *(float4*)&Bs[br][bc + 4] = pb1;
        __syncthreads();

        if (k0 + 8 < 128) {
            pa  = *(const float4*)(Ap + k0 + 8);
            pb0 = *(const float4*)(Bp + (size_t)(k0 + 8) * ldb);
            pb1 = *(const float4*)(Bp + (size_t)(k0 + 8) * ldb + 4);
        }

#pragma unroll
        for (int kk = 0; kk < 8; kk++) {
            const ulonglong2 a01 = *(const ulonglong2*)&As[kk][ty * 8];
            const ulonglong2 a23 = *(const ulonglong2*)&As[kk][ty * 8 + 4];
            const float4 b0 = *(const float4*)&Bs[kk][tx * 8];
            const float4 b1 = *(const float4*)&Bs[kk][tx * 8 + 4];
            const float bsc[8] = {b0.x, b0.y, b0.z, b0.w, b1.x, b1.y, b1.z, b1.w};
#pragma unroll
            for (int j = 0; j < 8; j++) {
                const u64 bd = pack2(bsc[j], bsc[j]);
                acc[0][j] = fma2(a01.x, bd, acc[0][j]);
                acc[1][j] = fma2(a01.y, bd, acc[1][j]);
                acc[2][j] = fma2(a23.x, bd, acc[2][j]);
                acc[3][j] = fma2(a23.y, bd, acc[3][j]);
            }
        }
        __syncthreads();
    }

    const int orow = row0 + ty * 8;
    const int ocol = col0 + tx * 8;
#pragma unroll
    for (int p = 0; p < 4; p++) {
        float2 u0 = unpack2(acc[p][0]);
        float2 u1 = unpack2(acc[p][1]);
        float2 u2 = unpack2(acc[p][2]);
        float2 u3 = unpack2(acc[p][3]);
        float2 u4 = unpack2(acc[p][4]);
        float2 u5 = unpack2(acc[p][5]);
        float2 u6 = unpack2(acc[p][6]);
        float2 u7 = unpack2(acc[p][7]);
        float* r0 = P + (size_t)(orow + 2 * p) * ldp + ocol;
        float* r1 = r0 + ldp;
        *(float4*)r0       = make_float4(u0.x, u1.x, u2.x, u3.x);
        *(float4*)(r0 + 4) = make_float4(u4.x, u5.x, u6.x, u7.x);
        *(float4*)r1       = make_float4(u0.y, u1.y, u2.y, u3.y);
        *(float4*)(r1 + 4) = make_float4(u4.y, u5.y, u6.y, u7.y);
    }
}

// Stage 1a: split-K partials for K = h1@w1 (which=0) and Q = h2@w2 (which=1).
__global__ void __launch_bounds__(128, 4)
qk_gemm_split(const float* __restrict__ h1, const float* __restrict__ h2,
              const float* __restrict__ w)
{
    const int which = blockIdx.z >> 2;
    const int ks    = blockIdx.z & 3;
    const int k0    = ks * 128;
    const float* A  = (which ? h2 : h1) + k0;
    const float* Bm = w + (size_t)which * EE * UU + (size_t)k0 * UU;
    float* P = g_part + (size_t)(ks * 2 + which) * 2048 * 256;
    sgemm_64x128_k128(A, Bm, P, EE, UU, 256, blockIdx.y * 64, blockIdx.x * 128);
}

// Stage 1b: reduce partials -> g_K (+b1), g_Q. grid 1024, block 256.
__global__ void __launch_bounds__(256)
qk_reduce(const float* __restrict__ b1)
{
    const int t = blockIdx.x * 256 + threadIdx.x;
    const int which = t >> 17;
    const int i4 = t & 131071;
    const float4* p = (const float4*)g_part + (size_t)which * 131072 + i4;
    float4 s0 = p[0];
    float4 s1 = p[262144];
    float4 s2 = p[524288];
    float4 s3 = p[786432];
    float4 o = make_float4((s0.x + s1.x) + (s2.x + s3.x),
                           (s0.y + s1.y) + (s2.y + s3.y),
                           (s0.z + s1.z) + (s2.z + s3.z),
                           (s0.w + s1.w) + (s2.w + s3.w));
    if (which == 0) {
        const float4 bv = ((const float4*)b1)[i4 & 63];
        o.x += bv.x; o.y += bv.y; o.z += bv.z; o.w += bv.w;
        ((float4*)g_K)[i4] = o;
    } else {
        ((float4*)g_Q)[i4] = o;
    }
}

// Stage 3a: split-K partials for out[b] = P[b] @ h1[b].
__global__ void __launch_bounds__(128, 4)
pv_gemm_split(const float* __restrict__ h1)
{
    const int b  = blockIdx.z >> 2;
    const int ks = blockIdx.z & 3;
    const int k0 = ks * 128;
    const float* A  = g_S + (size_t)b * SS * SS + k0;
    const float* Bm = h1  + (size_t)b * SS * EE + (size_t)k0 * EE;
    float* P = g_part + (size_t)ks * 2048 * 512 + (size_t)b * 512 * 512;
    sgemm_64x128_k128(A, Bm, P, SS, EE, 512, blockIdx.y * 64, blockIdx.x * 128);
}

// Stage 3b: reduce partials -> out. grid 1024, block 256.
__global__ void __launch_bounds__(256)
pv_reduce(float* __restrict__ out)
{
    const int i4 = blockIdx.x * 256 + threadIdx.x;
    const float4* p = (const float4*)g_part + i4;
    float4 s0 = p[0];
    float4 s1 = p[262144];
    float4 s2 = p[524288];
    float4 s3 = p[786432];
    ((float4*)out)[i4] = make_float4((s0.x + s1.x) + (s2.x + s3.x),
                                     (s0.y + s1.y) + (s2.y + s3.y),
                                     (s0.z + s1.z) + (s2.z + s3.z),
                                     (s0.w + s1.w) + (s2.w + s3.w));
}

// ---------------------------------------------------------------------------
// Stage 2a: scores[b,i,j] = sum_u v[u]*tanh(Q[b,i,u]+K[b,j,u])
// (b2 dropped: softmax is shift-invariant.)
// 32(i) x 32(j) tile, 256 threads, MUFU-floor bound (measured ~51us).
// grid (16 jt, 16 it, 4 b).
// ---------------------------------------------------------------------------
__global__ void __launch_bounds__(256)
scores_kernel(const float* __restrict__ v)
{
    __shared__ float4 q4[32][32];   // [i][u4]
    __shared__ float4 k4[32][33];   // padded
    __shared__ float4 v4s[32];

    const int b  = blockIdx.z;
    const int it = blockIdx.y;
    const int jt = blockIdx.x;
    const int tid = threadIdx.x;
    const int jl = tid & 31;        // local j (lane)
    const int ib = tid >> 5;        // local i base (0..7)

    const float* Qb = g_Q + ((size_t)(b * SS + it * 32)) * UU;
    const float* Kb = g_K + ((size_t)(b * SS + jt * 32)) * UU;

    float acc[4] = {0.f, 0.f, 0.f, 0.f};

    for (int uc = 0; uc < 2; uc++) {
        const int base = uc * 32;   // float4 offset within row
        for (int t = tid; t < 32 * 32; t += 256) {
            const int r = t >> 5, c = t & 31;
            q4[r][c] = ((const float4*)(Qb + (size_t)r * UU))[base + c];
            k4[r][c] = ((const float4*)(Kb + (size_t)r * UU))[base + c];
        }
        if (tid < 32) v4s[tid] = ((const float4*)v)[base + tid];
        __syncthreads();

#pragma unroll 4
        for (int c = 0; c < 32; c++) {
            const float4 kv = k4[jl][c];
            const float4 vv = v4s[c];
#pragma unroll
            for (int r = 0; r < 4; r++) {
                const float4 qv = q4[ib + 8 * r][c];   // warp broadcast
                acc[r] += vv.x * tanh_ap(qv.x + kv.x);
                acc[r] += vv.y * tanh_ap(qv.y + kv.y);
                acc[r] += vv.z * tanh_ap(qv.z + kv.z);
                acc[r] += vv.w * tanh_ap(qv.w + kv.w);
            }
        }
        __syncthreads();
    }

#pragma unroll
    for (int r = 0; r < 4; r++) {
        const int i = it * 32 + ib + 8 * r;
        g_S[((size_t)(b * SS + i)) * SS + jt * 32 + jl] = acc[r];
    }
}

// Stage 2b: in-place row softmax over j (rows of 512). grid 2048, block 256.
__global__ void __launch_bounds__(256)
softmax_kernel()
{
    const int row = blockIdx.x;
    float* p = g_S + (size_t)row * SS;
    const int tid = threadIdx.x;

    float v0 = p[tid];
    float v1 = p[tid + 256];
    float m = fmaxf(v0, v1);
#pragma unroll
    for (int o = 16; o > 0; o >>= 1) m = fmaxf(m, __shfl_xor_sync(0xffffffffu, m, o));
    __shared__ float sm[8];
    __shared__ float ssum[8];
    if ((tid & 31) == 0) sm[tid >> 5] = m;
    __syncthreads();
    float bm = sm[0];
#pragma unroll
    for (int i = 1; i < 8; i++) bm = fmaxf(bm, sm[i]);

    const float L2E = 1.4426950408889634f;
    float e0 = ex2_ap((v0 - bm) * L2E);
    float e1 = ex2_ap((v1 - bm) * L2E);
    float s = e0 + e1;
#pragma unroll
    for (int o = 16; o > 0; o >>= 1) s += __shfl_xor_sync(0xffffffffu, s, o);
    if ((tid & 31) == 0) ssum[tid >> 5] = s;
    __syncthreads();
    float bs = 0.f;
#pragma unroll
    for (int i = 0; i < 8; i++) bs += ssum[i];

    const float inv = 1.0f / bs;
    p[tid]       = e0 * inv;
    p[tid + 256] = e1 * inv;
}

extern "C" void kernel_launch(void* const* d_in, const int* in_sizes, int n_in,
                              void* d_out, int out_size)
{
    const float* h1 = (const float*)d_in[0];
    const float* h2 = (const float*)d_in[1];
    const float* w  = (const float*)d_in[2];
    const float* b1 = (const float*)d_in[3];
    const float* v  = (const float*)d_in[4];
    // b2 (d_in[5]) unused: softmax is shift-invariant.
    float* out = (float*)d_out;

    dim3 gA(UU / 128, (BB * SS) / 64, 2 * KSPLIT);  // (2, 32, 8) = 512 CTAs
    qk_gemm_split<<<gA, 128>>>(h1, h2, w);
    qk_reduce<<<1024, 256>>>(b1);

    dim3 gB(SS / 32, SS / 32, BB);                  // (16, 16, 4) = 1024 CTAs
    scores_kernel<<<gB, 256>>>(v);

    softmax_kernel<<<BB * SS, 256>>>();             // 2048 rows

    dim3 gD(EE / 128, SS / 64, BB * KSPLIT);        // (4, 8, 16) = 512 CTAs
    pv_gemm_split<<<gD, 128>>>(h1);
    pv_reduce<<<1024, 256>>>(out);
}

// round 9
// speedup vs baseline: 1.2473x; 1.0140x over previous
#include <cuda_runtime.h>
#include <cuda_bf16.h>

#define BB 4
#define SS 512
#define EE 512
#define UU 256
#define KSPLIT 4

// Scratch (__device__ globals, allocation-free rule)
__device__ float g_K[BB * SS * UU];            // key_pre + b1
__device__ float g_Q[BB * SS * UU];            // qry_pre
__device__ float g_S[BB * SS * SS];            // scores -> probs
__device__ float g_part[KSPLIT * 2048 * 512];  // 16MB split-K partials (shared)

typedef unsigned long long u64;

__device__ __forceinline__ u64 pack2(float x, float y) {
    u64 r; asm("mov.b64 %0,{%1,%2};" : "=l"(r) : "f"(x), "f"(y)); return r;
}
__device__ __forceinline__ u64 fma2(u64 a, u64 b, u64 c) {
    u64 d; asm("fma.rn.f32x2 %0,%1,%2,%3;" : "=l"(d) : "l"(a), "l"(b), "l"(c)); return d;
}
__device__ __forceinline__ float2 unpack2(u64 v) {
    float2 f; asm("mov.b64 {%0,%1},%2;" : "=f"(f.x), "=f"(f.y) : "l"(v)); return f;
}
__device__ __forceinline__ float tanh_ap(float x) {
    float y; asm("tanh.approx.f32 %0,%1;" : "=f"(y) : "f"(x)); return y;
}
__device__ __forceinline__ float ex2_ap(float x) {
    float y; asm("ex2.approx.f32 %0,%1;" : "=f"(y) : "f"(x)); return y;
}

// ---------------------------------------------------------------------------
// 64(M) x 128(N) tile x K=128 chunk SGEMM. 128 threads, 8x8 micro, FFMA2
// with M-packed accumulators. BK=8, register-prefetch + DOUBLE-BUFFERED smem
// (one __syncthreads per chunk: the store to buffer (c+1)&1 overlaps compute
// on buffer c&1, and post-barrier LDS latency overlaps the FFMA2 tail).
// ---------------------------------------------------------------------------
__device__ __forceinline__ void sgemm_64x128_k128(
    const float* __restrict__ A, const float* __restrict__ B,
    float* __restrict__ P, int lda, int ldb, int ldp,
    int row0, int col0)
{
    __shared__ __align__(16) float As[2][8][64];    // [buf][k][m]
    __shared__ __align__(16) float Bs[2][8][128];   // [buf][k][n]

    const int tid = threadIdx.x;
    const int tx = tid & 15;          // N micro group (8 cols)
    const int ty = tid >> 4;          // M micro group (8 rows)
    const int ar = tid >> 1;          // A load: m row 0..63
    const int ak = (tid & 1) * 4;     // A load: k base 0/4
    const int br = tid >> 4;          // B load: k row 0..7
    const int bc = (tid & 15) * 8;    // B load: n col 0..120

    const float* Ap = A + (size_t)(row0 + ar) * lda + ak;
    const float* Bp = B + (size_t)br * ldb + col0 + bc;

    // chunk 0 -> buffer 0
    float4 pa  = *(const float4*)Ap;
    float4 pb0 = *(const float4*)Bp;
    float4 pb1 = *(const float4*)(Bp + 4);
    As[0][ak + 0][ar] = pa.x;
    As[0][ak + 1][ar] = pa.y;
    As[0][ak + 2][ar] = pa.z;
    As[0][ak + 3][ar] = pa.w;
    *(float4*)&Bs[0][br][bc]     = pb0;
    *(float4*)&Bs[0][br][bc + 4] = pb1;
    __syncthreads();

    u64 acc[4][8];
#pragma unroll
    for (int p = 0; p < 4; p++)
#pragma unroll
        for (int j = 0; j < 8; j++) acc[p][j] = 0ull;

#pragma unroll 1
    for (int c = 0; c < 16; c++) {
        const int buf = c & 1;
        // prefetch chunk c+1 into registers (gmem latency hidden by compute)
        if (c < 15) {
            const int k1 = (c + 1) * 8;
            pa  = *(const float4*)(Ap + k1);
            pb0 = *(const float4*)(Bp + (size_t)k1 * ldb);
            pb1 = *(const float4*)(Bp + (size_t)k1 * ldb + 4);
        }

#pragma unroll
        for (int kk = 0; kk < 8; kk++) {
            const ulonglong2 a01 = *(const ulonglong2*)&As[buf][kk][ty * 8];
            const ulonglong2 a23 = *(const ulonglong2*)&As[buf][kk][ty * 8 + 4];
            const float4 b0 = *(const float4*)&Bs[buf][kk][tx * 8];
            const float4 b1 = *(const float4*)&Bs[buf][kk][tx * 8 + 4];
            const float bsc[8] = {b0.x, b0.y, b0.z, b0.w, b1.x, b1.y, b1.z, b1.w};
#pragma unroll
            for (int j = 0; j < 8; j++) {
                const u64 bd = pack2(bsc[j], bsc[j]);
                acc[0][j] = fma2(a01.x, bd, acc[0][j]);
                acc[1][j] = fma2(a01.y, bd, acc[1][j]);
                acc[2][j] = fma2(a23.x, bd, acc[2][j]);
                acc[3][j] = fma2(a23.y, bd, acc[3][j]);
            }
        }

        // store chunk c+1 into the OTHER buffer (no one reads it yet),
        // then a single barrier makes it visible for the next iteration.
        if (c < 15) {
            const int nb = buf ^ 1;
            As[nb][ak + 0][ar] = pa.x;
            As[nb][ak + 1][ar] = pa.y;
            As[nb][ak + 2][ar] = pa.z;
            As[nb][ak + 3][ar] = pa.w;
            *(float4*)&Bs[nb][br][bc]     = pb0;
            *(float4*)&Bs[nb][br][bc + 4] = pb1;
            __syncthreads();
        }
    }

    const int orow = row0 + ty * 8;
    const int ocol = col0 + tx * 8;
#pragma unroll
    for (int p = 0; p < 4; p++) {
        float2 u0 = unpack2(acc[p][0]);
        float2 u1 = unpack2(acc[p][1]);
        float2 u2 = unpack2(acc[p][2]);
        float2 u3 = unpack2(acc[p][3]);
        float2 u4 = unpack2(acc[p][4]);
        float2 u5 = unpack2(acc[p][5]);
        float2 u6 = unpack2(acc[p][6]);
        float2 u7 = unpack2(acc[p][7]);
        float* r0 = P + (size_t)(orow + 2 * p) * ldp + ocol;
        float* r1 = r0 + ldp;
        *(float4*)r0       = make_float4(u0.x, u1.x, u2.x, u3.x);
        *(float4*)(r0 + 4) = make_float4(u4.x, u5.x, u6.x, u7.x);
        *(float4*)r1       = make_float4(u0.y, u1.y, u2.y, u3.y);
        *(float4*)(r1 + 4) = make_float4(u4.y, u5.y, u6.y, u7.y);
    }
}

// Stage 1a: split-K partials for K = h1@w1 (which=0) and Q = h2@w2 (which=1).
__global__ void __launch_bounds__(128, 4)
qk_gemm_split(const float* __restrict__ h1, const float* __restrict__ h2,
              const float* __restrict__ w)
{
    const int which = blockIdx.z >> 2;
    const int ks    = blockIdx.z & 3;
    const int k0    = ks * 128;
    const float* A  = (which ? h2 : h1) + k0;
    const float* Bm = w + (size_t)which * EE * UU + (size_t)k0 * UU;
    float* P = g_part + (size_t)(ks * 2 + which) * 2048 * 256;
    sgemm_64x128_k128(A, Bm, P, EE, UU, 256, blockIdx.y * 64, blockIdx.x * 128);
}

// Stage 1b: reduce partials -> g_K (+b1), g_Q. grid 1024, block 256.
__global__ void __launch_bounds__(256)
qk_reduce(const float* __restrict__ b1)
{
    const int t = blockIdx.x * 256 + threadIdx.x;
    const int which = t >> 17;
    const int i4 = t & 131071;
    const float4* p = (const float4*)g_part + (size_t)which * 131072 + i4;
    float4 s0 = p[0];
    float4 s1 = p[262144];
    float4 s2 = p[524288];
    float4 s3 = p[786432];
    float4 o = make_float4((s0.x + s1.x) + (s2.x + s3.x),
                           (s0.y + s1.y) + (s2.y + s3.y),
                           (s0.z + s1.z) + (s2.z + s3.z),
                           (s0.w + s1.w) + (s2.w + s3.w));
    if (which == 0) {
        const float4 bv = ((const float4*)b1)[i4 & 63];
        o.x += bv.x; o.y += bv.y; o.z += bv.z; o.w += bv.w;
        ((float4*)g_K)[i4] = o;
    } else {
        ((float4*)g_Q)[i4] = o;
    }
}

// Stage 3a: split-K partials for out[b] = P[b] @ h1[b].
__global__ void __launch_bounds__(128, 4)
pv_gemm_split(const float* __restrict__ h1)
{
    const int b  = blockIdx.z >> 2;
    const int ks = blockIdx.z & 3;
    const int k0 = ks * 128;
    const float* A  = g_S + (size_t)b * SS * SS + k0;
    const float* Bm = h1  + (size_t)b * SS * EE + (size_t)k0 * EE;
    float* P = g_part + (size_t)ks * 2048 * 512 + (size_t)b * 512 * 512;
    sgemm_64x128_k128(A, Bm, P, SS, EE, 512, blockIdx.y * 64, blockIdx.x * 128);
}

// Stage 3b: reduce partials -> out. grid 1024, block 256.
__global__ void __launch_bounds__(256)
pv_reduce(float* __restrict__ out)
{
    const int i4 = blockIdx.x * 256 + threadIdx.x;
    const float4* p = (const float4*)g_part + i4;
    float4 s0 = p[0];
    float4 s1 = p[262144];
    float4 s2 = p[524288];
    float4 s3 = p[786432];
    ((float4*)out)[i4] = make_float4((s0.x + s1.x) + (s2.x + s3.x),
                                     (s0.y + s1.y) + (s2.y + s3.y),
                                     (s0.z + s1.z) + (s2.z + s3.z),
                                     (s0.w + s1.w) + (s2.w + s3.w));
}

// ---------------------------------------------------------------------------
// Stage 2a: scores[b,i,j] = sum_u v[u]*tanh(Q[b,i,u]+K[b,j,u])
// (b2 dropped: softmax is shift-invariant.) At MUFU floor (~51us).
// ---------------------------------------------------------------------------
__global__ void __launch_bounds__(256)
scores_kernel(const float* __restrict__ v)
{
    __shared__ float4 q4[32][32];   // [i][u4]
    __shared__ float4 k4[32][33];   // padded
    __shared__ float4 v4s[32];

    const int b  = blockIdx.z;
    const int it = blockIdx.y;
    const int jt = blockIdx.x;
    const int tid = threadIdx.x;
    const int jl = tid & 31;        // local j (lane)
    const int ib = tid >> 5;        // local i base (0..7)

    const float* Qb = g_Q + ((size_t)(b * SS + it * 32)) * UU;
    const float* Kb = g_K + ((size_t)(b * SS + jt * 32)) * UU;

    float acc[4] = {0.f, 0.f, 0.f, 0.f};

    for (int uc = 0; uc < 2; uc++) {
        const int base = uc * 32;   // float4 offset within row
        for (int t = tid; t < 32 * 32; t += 256) {
            const int r = t >> 5, c = t & 31;
            q4[r][c] = ((const float4*)(Qb + (size_t)r * UU))[base + c];
            k4[r][c] = ((const float4*)(Kb + (size_t)r * UU))[base + c];
        }
        if (tid < 32) v4s[tid] = ((const float4*)v)[base + tid];
        __syncthreads();

#pragma unroll 4
        for (int c = 0; c < 32; c++) {
            const float4 kv = k4[jl][c];
            const float4 vv = v4s[c];
#pragma unroll
            for (int r = 0; r < 4; r++) {
                const float4 qv = q4[ib + 8 * r][c];   // warp broadcast
                acc[r] += vv.x * tanh_ap(qv.x + kv.x);
                acc[r] += vv.y * tanh_ap(qv.y + kv.y);
                acc[r] += vv.z * tanh_ap(qv.z + kv.z);
                acc[r] += vv.w * tanh_ap(qv.w + kv.w);
            }
        }
        __syncthreads();
    }

#pragma unroll
    for (int r = 0; r < 4; r++) {
        const int i = it * 32 + ib + 8 * r;
        g_S[((size_t)(b * SS + i)) * SS + jt * 32 + jl] = acc[r];
    }
}

// Stage 2b: in-place row softmax over j (rows of 512). grid 2048, block 256.
__global__ void __launch_bounds__(256)
softmax_kernel()
{
    const int row = blockIdx.x;
    float* p = g_S + (size_t)row * SS;
    const int tid = threadIdx.x;

    float v0 = p[tid];
    float v1 = p[tid + 256];
    float m = fmaxf(v0, v1);
#pragma unroll
    for (int o = 16; o > 0; o >>= 1) m = fmaxf(m, __shfl_xor_sync(0xffffffffu, m, o));
    __shared__ float sm[8];
    __shared__ float ssum[8];
    if ((tid & 31) == 0) sm[tid >> 5] = m;
    __syncthreads();
    float bm = sm[0];
#pragma unroll
    for (int i = 1; i < 8; i++) bm = fmaxf(bm, sm[i]);

    const float L2E = 1.4426950408889634f;
    float e0 = ex2_ap((v0 - bm) * L2E);
    float e1 = ex2_ap((v1 - bm) * L2E);
    float s = e0 + e1;
#pragma unroll
    for (int o = 16; o > 0; o >>= 1) s += __shfl_xor_sync(0xffffffffu, s, o);
    if ((tid & 31) == 0) ssum[tid >> 5] = s;
    __syncthreads();
    float bs = 0.f;
#pragma unroll
    for (int i = 0; i < 8; i++) bs += ssum[i];

    const float inv = 1.0f / bs;
    p[tid]       = e0 * inv;
    p[tid + 256] = e1 * inv;
}

extern "C" void kernel_launch(void* const* d_in, const int* in_sizes, int n_in,
                              void* d_out, int out_size)
{
    const float* h1 = (const float*)d_in[0];
    const float* h2 = (const float*)d_in[1];
    const float* w  = (const float*)d_in[2];
    const float* b1 = (const float*)d_in[3];
    const float* v  = (const float*)d_in[4];
    // b2 (d_in[5]) unused: softmax is shift-invariant.
    float* out = (float*)d_out;

    dim3 gA(UU / 128, (BB * SS) / 64, 2 * KSPLIT);  // (2, 32, 8) = 512 CTAs
    qk_gemm_split<<<gA, 128>>>(h1, h2, w);
    qk_reduce<<<1024, 256>>>(b1);

    dim3 gB(SS / 32, SS / 32, BB);                  // (16, 16, 4) = 1024 CTAs
    scores_kernel<<<gB, 256>>>(v);

    softmax_kernel<<<BB * SS, 256>>>();             // 2048 rows

    dim3 gD(EE / 128, SS / 64, BB * KSPLIT);        // (4, 8, 16) = 512 CTAs
    pv_gemm_split<<<gD, 128>>>(h1);
    pv_reduce<<<1024, 256>>>(out);
}

// round 10
// speedup vs baseline: 1.3688x; 1.0975x over previous
#include <cuda_runtime.h>
#include <cuda_bf16.h>

#define BB 4
#define SS 512
#define EE 512
#define UU 256

// ---------------- scratch (__device__ globals) ----------------
__device__ float g_K[BB * SS * UU];            // key_pre + b1 (fp32, scores input)
__device__ float g_Q[BB * SS * UU];            // qry_pre
__device__ float g_S[BB * SS * SS];            // raw scores (fp32)
__device__ float g_part[4 * 2048 * 512];       // 16MB split-K partials

// bf16 hi/lo planes, stored as u32 = (bf16 x_{2k+1} << 16) | bf16 x_{2k}
__device__ unsigned g_AH[2 * 2048 * 256];      // h1,h2 row-major [which][row][k-pair]
__device__ unsigned g_AL[2 * 2048 * 256];
__device__ unsigned g_WH[2 * 256 * 256];       // w transposed [which][u][e-pair]
__device__ unsigned g_WL[2 * 256 * 256];
__device__ unsigned g_TH[4 * 512 * 256];       // h1 transposed [b][e][j-pair]
__device__ unsigned g_TL[4 * 512 * 256];
__device__ unsigned g_SH[2048 * 256];          // softmax probs [row][j-pair]
__device__ unsigned g_SL[2048 * 256];

// ---------------- helpers ----------------
__device__ __forceinline__ float tanh_ap(float x) {
    float y; asm("tanh.approx.f32 %0,%1;" : "=f"(y) : "f"(x)); return y;
}
__device__ __forceinline__ float ex2_ap(float x) {
    float y; asm("ex2.approx.f32 %0,%1;" : "=f"(y) : "f"(x)); return y;
}
__device__ __forceinline__ void cp16(void* dst, const void* src) {
    unsigned d = (unsigned)__cvta_generic_to_shared(dst);
    asm volatile("cp.async.ca.shared.global [%0],[%1],16;" :: "r"(d), "l"(src) : "memory");
}
// split (x0,x1) into bf16 hi/lo pair-packed u32s; lo is the exact fp32 residual
// rounded to bf16 (dropped lo*lo product term ~2^-18 relative).
__device__ __forceinline__ void bsplit2(float x0, float x1, unsigned& hi, unsigned& lo) {
    asm("cvt.rn.bf16x2.f32 %0, %1, %2;" : "=r"(hi) : "f"(x1), "f"(x0));
    float b0 = __uint_as_float(hi << 16);
    float b1 = __uint_as_float(hi & 0xffff0000u);
    float l0 = x0 - b0;
    float l1 = x1 - b1;
    asm("cvt.rn.bf16x2.f32 %0, %1, %2;" : "=r"(lo) : "f"(l1), "f"(l0));
}
__device__ __forceinline__ void mma16816(float* c, unsigned a0, unsigned a1,
                                         unsigned a2, unsigned a3,
                                         unsigned b0, unsigned b1) {
    asm volatile(
        "mma.sync.aligned.m16n8k16.row.col.f32.bf16.bf16.f32 "
        "{%0,%1,%2,%3}, {%4,%5,%6,%7}, {%8,%9}, {%0,%1,%2,%3};"
        : "+f"(c[0]), "+f"(c[1]), "+f"(c[2]), "+f"(c[3])
        : "r"(a0), "r"(a1), "r"(a2), "r"(a3), "r"(b0), "r"(b1));
}

// ---------------------------------------------------------------------------
// Conversion kernels (run once, at fp32 read bandwidth).
// ---------------------------------------------------------------------------
// h1 then h2 -> row-major planes. grid 2048 x 256; i = float4 index.
__global__ void __launch_bounds__(256)
conv_rows(const float* __restrict__ h1, const float* __restrict__ h2)
{
    const int i = blockIdx.x * 256 + threadIdx.x;           // 0..524287
    float4 v = (i < 262144) ? ((const float4*)h1)[i]
                            : ((const float4*)h2)[i - 262144];
    unsigned h0, l0, h1u, l1u;
    bsplit2(v.x, v.y, h0, l0);
    bsplit2(v.z, v.w, h1u, l1u);
    ((uint2*)g_AH)[i] = make_uint2(h0, h1u);
    ((uint2*)g_AL)[i] = make_uint2(l0, l1u);
}

// w [1024 e'][256 u] -> wT planes [which][u][e-pair]. grid (8, 32) x 256.
__global__ void __launch_bounds__(256)
conv_w(const float* __restrict__ w)
{
    __shared__ float tsm[32][33];
    const int tx = threadIdx.x & 31, ty = threadIdx.x >> 5;
    const int c0 = blockIdx.x * 32;       // u
    const int r0 = blockIdx.y * 32;       // e' in [0,1024)
#pragma unroll
    for (int j = 0; j < 4; j++)
        tsm[ty + 8 * j][tx] = w[(size_t)(r0 + ty + 8 * j) * UU + c0 + tx];
    __syncthreads();
    const int oc = threadIdx.x >> 3;      // 0..31
    const int p  = threadIdx.x & 7;
    const int which = r0 >> 9;
    const int rl = r0 & 511;
    unsigned* oH = g_WH + which * 65536;
    unsigned* oL = g_WL + which * 65536;
    const size_t base = (size_t)(c0 + oc) * 256 + (rl >> 1);
    unsigned h0, l0, h1u, l1u;
    bsplit2(tsm[2 * p][oc],      tsm[2 * p + 1][oc],  h0, l0);
    bsplit2(tsm[2 * p + 16][oc], tsm[2 * p + 17][oc], h1u, l1u);
    oH[base + p] = h0;      oL[base + p] = l0;
    oH[base + p + 8] = h1u; oL[base + p + 8] = l1u;
}

// h1 [b][j][e] -> transposed planes [b][e][j-pair]. grid (16, 16, 4) x 256.
__global__ void __launch_bounds__(256)
conv_h1T(const float* __restrict__ h1)
{
    __shared__ float tsm[32][33];
    const int tx = threadIdx.x & 31, ty = threadIdx.x >> 5;
    const int r0 = blockIdx.x * 32;       // j
    const int c0 = blockIdx.y * 32;       // e
    const int b  = blockIdx.z;
    const float* src = h1 + (size_t)b * SS * EE;
#pragma unroll
    for (int j = 0; j < 4; j++)
        tsm[ty + 8 * j][tx] = src[(size_t)(r0 + ty + 8 * j) * EE + c0 + tx];
    __syncthreads();
    const int oc = threadIdx.x >> 3;
    const int p  = threadIdx.x & 7;
    unsigned* oH = g_TH + (size_t)b * 131072;
    unsigned* oL = g_TL + (size_t)b * 131072;
    const size_t base = (size_t)(c0 + oc) * 256 + (r0 >> 1);
    unsigned h0, l0, h1u, l1u;
    bsplit2(tsm[2 * p][oc],      tsm[2 * p + 1][oc],  h0, l0);
    bsplit2(tsm[2 * p + 16][oc], tsm[2 * p + 17][oc], h1u, l1u);
    oH[base + p] = h0;      oL[base + p] = l0;
    oH[base + p + 8] = h1u; oL[base + p + 8] = l1u;
}

// ---------------------------------------------------------------------------
// 64x64 tile x K=128 chunk GEMM via mma.sync bf16 3x-split.
// 128 threads = 4 warps; warp w owns rows 16w..16w+15 of the tile.
// A,B given as u32 pair-planes with row stride 256 u32 (K=512 total).
// cp.async double-buffered k16 chunks; conflict-free padded smem.
// ---------------------------------------------------------------------------
__device__ __forceinline__ void mma_tile(
    const unsigned* __restrict__ AH, const unsigned* __restrict__ AL,
    const unsigned* __restrict__ BH, const unsigned* __restrict__ BL,
    float* __restrict__ P, int ldp, int row0, int col0, int ku0)
{
    __shared__ unsigned sA[2][2][64][12];   // [buf][plane][row][u32] (8 used, pad 12)
    __shared__ unsigned sB[2][2][64][12];

    const int tid = threadIdx.x;
    const int w = tid >> 5, lane = tid & 31;
    const int g = lane >> 2, t = lane & 3;
    const int fr = tid >> 1;              // fill row 0..63
    const int fh = (tid & 1) << 2;        // fill u32 col 0/4

    const unsigned* arH = AH + (size_t)(row0 + fr) * 256 + ku0 + fh;
    const unsigned* arL = AL + (size_t)(row0 + fr) * 256 + ku0 + fh;
    const unsigned* brH = BH + (size_t)(col0 + fr) * 256 + ku0 + fh;
    const unsigned* brL = BL + (size_t)(col0 + fr) * 256 + ku0 + fh;

    float acc[8][4];
#pragma unroll
    for (int i = 0; i < 8; i++)
#pragma unroll
        for (int j = 0; j < 4; j++) acc[i][j] = 0.f;

    // prefetch chunk 0
    cp16(&sA[0][0][fr][fh], arH);
    cp16(&sA[0][1][fr][fh], arL);
    cp16(&sB[0][0][fr][fh], brH);
    cp16(&sB[0][1][fr][fh], brL);
    asm volatile("cp.async.commit_group;");

#pragma unroll 1
    for (int c = 0; c < 8; c++) {
        const int buf = c & 1;
        asm volatile("cp.async.wait_group 0;");
        __syncthreads();
        if (c < 7) {
            const int nb = buf ^ 1;
            const int off = (c + 1) * 8;
            cp16(&sA[nb][0][fr][fh], arH + off);
            cp16(&sA[nb][1][fr][fh], arL + off);
            cp16(&sB[nb][0][fr][fh], brH + off);
            cp16(&sB[nb][1][fr][fh], brL + off);
            asm volatile("cp.async.commit_group;");
        }

        const int ra = 16 * w + g;
        const unsigned aH0 = sA[buf][0][ra][t];
        const unsigned aH1 = sA[buf][0][ra + 8][t];
        const unsigned aH2 = sA[buf][0][ra][t + 4];
        const unsigned aH3 = sA[buf][0][ra + 8][t + 4];
        const unsigned aL0 = sA[buf][1][ra][t];
        const unsigned aL1 = sA[buf][1][ra + 8][t];
        const unsigned aL2 = sA[buf][1][ra][t + 4];
        const unsigned aL3 = sA[buf][1][ra + 8][t + 4];
#pragma unroll
        for (int nt = 0; nt < 8; nt++) {
            const unsigned bH0 = sB[buf][0][8 * nt + g][t];
            const unsigned bH1 = sB[buf][0][8 * nt + g][t + 4];
            const unsigned bL0 = sB[buf][1][8 * nt + g][t];
            const unsigned bL1 = sB[buf][1][8 * nt + g][t + 4];
            mma16816(acc[nt], aH0, aH1, aH2, aH3, bH0, bH1);
            mma16816(acc[nt], aH0, aH1, aH2, aH3, bL0, bL1);
            mma16816(acc[nt], aL0, aL1, aL2, aL3, bH0, bH1);
        }
        // next-iteration's top barrier orders buffer reuse; no second sync needed
    }

    const int orow = row0 + 16 * w + g;
#pragma unroll
    for (int nt = 0; nt < 8; nt++) {
        const int ocol = col0 + 8 * nt + 2 * t;
        *(float2*)&P[(size_t)orow * ldp + ocol] = make_float2(acc[nt][0], acc[nt][1]);
        *(float2*)&P[(size_t)(orow + 8) * ldp + ocol] = make_float2(acc[nt][2], acc[nt][3]);
    }
}

// Stage 1a: split-K partials, K = h1@w1 (which=0), Q = h2@w2 (which=1).
// grid (4, 32, 8 = which*4+ks), block 128 -> 1024 CTAs.
__global__ void __launch_bounds__(128)
qk_mma_split()
{
    const int which = blockIdx.z >> 2;
    const int ks    = blockIdx.z & 3;
    float* P = g_part + (size_t)(ks * 2 + which) * 2048 * 256;
    mma_tile(g_AH + (size_t)which * 524288, g_AL + (size_t)which * 524288,
             g_WH + which * 65536, g_WL + which * 65536,
             P, 256, blockIdx.y * 64, blockIdx.x * 64, ks * 64);
}

// Stage 1b: reduce partials -> g_K (+b1), g_Q. grid 1024, block 256.
__global__ void __launch_bounds__(256)
qk_reduce(const float* __restrict__ b1)
{
    const int tt = blockIdx.x * 256 + threadIdx.x;
    const int which = tt >> 17;
    const int i4 = tt & 131071;
    const float4* p = (const float4*)g_part + (size_t)which * 131072 + i4;
    float4 s0 = p[0];
    float4 s1 = p[262144];
    float4 s2 = p[524288];
    float4 s3 = p[786432];
    float4 o = make_float4((s0.x + s1.x) + (s2.x + s3.x),
                           (s0.y + s1.y) + (s2.y + s3.y),
                           (s0.z + s1.z) + (s2.z + s3.z),
                           (s0.w + s1.w) + (s2.w + s3.w));
    if (which == 0) {
        const float4 bv = ((const float4*)b1)[i4 & 63];
        o.x += bv.x; o.y += bv.y; o.z += bv.z; o.w += bv.w;
        ((float4*)g_K)[i4] = o;
    } else {
        ((float4*)g_Q)[i4] = o;
    }
}

// Stage 3a: split-K partials for out[b] = P[b] @ h1[b].
// grid (8, 8, 16 = b*4+ks), block 128 -> 1024 CTAs.
__global__ void __launch_bounds__(128)
pv_mma_split()
{
    const int b  = blockIdx.z >> 2;
    const int ks = blockIdx.z & 3;
    float* P = g_part + (size_t)ks * 2048 * 512 + (size_t)b * 512 * 512;
    mma_tile(g_SH + (size_t)b * 131072, g_SL + (size_t)b * 131072,
             g_TH + (size_t)b * 131072, g_TL + (size_t)b * 131072,
             P, 512, blockIdx.y * 64, blockIdx.x * 64, ks * 64);
}

// Stage 3b: reduce partials -> out. grid 1024, block 256.
__global__ void __launch_bounds__(256)
pv_reduce(float* __restrict__ out)
{
    const int i4 = blockIdx.x * 256 + threadIdx.x;
    const float4* p = (const float4*)g_part + i4;
    float4 s0 = p[0];
    float4 s1 = p[262144];
    float4 s2 = p[524288];
    float4 s3 = p[786432];
    ((float4*)out)[i4] = make_float4((s0.x + s1.x) + (s2.x + s3.x),
                                     (s0.y + s1.y) + (s2.y + s3.y),
                                     (s0.z + s1.z) + (s2.z + s3.z),
                                     (s0.w + s1.w) + (s2.w + s3.w));
}

// ---------------------------------------------------------------------------
// Stage 2a: scores (fp32, MUFU-floor bound, unchanged). b2 dropped.
// grid (16 jt, 16 it, 4 b), block 256.
// ---------------------------------------------------------------------------
__global__ void __launch_bounds__(256)
scores_kernel(const float* __restrict__ v)
{
    __shared__ float4 q4[32][32];
    __shared__ float4 k4[32][33];
    __shared__ float4 v4s[32];

    const int b  = blockIdx.z;
    const int it = blockIdx.y;
    const int jt = blockIdx.x;
    const int tid = threadIdx.x;
    const int jl = tid & 31;
    const int ib = tid >> 5;

    const float* Qb = g_Q + ((size_t)(b * SS + it * 32)) * UU;
    const float* Kb = g_K + ((size_t)(b * SS + jt * 32)) * UU;

    float acc[4] = {0.f, 0.f, 0.f, 0.f};

    for (int uc = 0; uc < 2; uc++) {
        const int base = uc * 32;
        for (int tix = tid; tix < 32 * 32; tix += 256) {
            const int r = tix >> 5, c = tix & 31;
            q4[r][c] = ((const float4*)(Qb + (size_t)r * UU))[base + c];
            k4[r][c] = ((const float4*)(Kb + (size_t)r * UU))[base + c];
        }
        if (tid < 32) v4s[tid] = ((const float4*)v)[base + tid];
        __syncthreads();

#pragma unroll 4
        for (int c = 0; c < 32; c++) {
            const float4 kv = k4[jl][c];
            const float4 vv = v4s[c];
#pragma unroll
            for (int r = 0; r < 4; r++) {
                const float4 qv = q4[ib + 8 * r][c];
                acc[r] += vv.x * tanh_ap(qv.x + kv.x);
                acc[r] += vv.y * tanh_ap(qv.y + kv.y);
                acc[r] += vv.z * tanh_ap(qv.z + kv.z);
                acc[r] += vv.w * tanh_ap(qv.w + kv.w);
            }
        }
        __syncthreads();
    }

#pragma unroll
    for (int r = 0; r < 4; r++) {
        const int i = it * 32 + ib + 8 * r;
        g_S[((size_t)(b * SS + i)) * SS + jt * 32 + jl] = acc[r];
    }
}

// Stage 2b: row softmax; emits bf16 hi/lo pair-planes for the pv mma.
// thread tid owns cols 2tid, 2tid+1. grid 2048, block 256.
__global__ void __launch_bounds__(256)
softmax2()
{
    const int row = blockIdx.x;
    const float* s = g_S + (size_t)row * SS;
    const int tid = threadIdx.x;

    const float2 vv = ((const float2*)s)[tid];
    float m = fmaxf(vv.x, vv.y);
#pragma unroll
    for (int o = 16; o > 0; o >>= 1) m = fmaxf(m, __shfl_xor_sync(0xffffffffu, m, o));
    __shared__ float sm[8];
    __shared__ float ssum[8];
    if ((tid & 31) == 0) sm[tid >> 5] = m;
    __syncthreads();
    float bm = sm[0];
#pragma unroll
    for (int i = 1; i < 8; i++) bm = fmaxf(bm, sm[i]);

    const float L2E = 1.4426950408889634f;
    float e0 = ex2_ap((vv.x - bm) * L2E);
    float e1 = ex2_ap((vv.y - bm) * L2E);
    float su = e0 + e1;
#pragma unroll
    for (int o = 16; o > 0; o >>= 1) su += __shfl_xor_sync(0xffffffffu, su, o);
    if ((tid & 31) == 0) ssum[tid >> 5] = su;
    __syncthreads();
    float bs = 0.f;
#pragma unroll
    for (int i = 0; i < 8; i++) bs += ssum[i];

    const float inv = 1.0f / bs;
    unsigned h, l;
    bsplit2(e0 * inv, e1 * inv, h, l);
    g_SH[(size_t)row * 256 + tid] = h;
    g_SL[(size_t)row * 256 + tid] = l;
}

extern "C" void kernel_launch(void* const* d_in, const int* in_sizes, int n_in,
                              void* d_out, int out_size)
{
    const float* h1 = (const float*)d_in[0];
    const float* h2 = (const float*)d_in[1];
    const float* w  = (const float*)d_in[2];
    const float* b1 = (const float*)d_in[3];
    const float* v  = (const float*)d_in[4];
    // b2 (d_in[5]) unused: softmax is shift-invariant.
    float* out = (float*)d_out;

    conv_rows<<<2048, 256>>>(h1, h2);
    conv_w<<<dim3(8, 32), 256>>>(w);
    conv_h1T<<<dim3(16, 16, 4), 256>>>(h1);

    qk_mma_split<<<dim3(4, 32, 8), 128>>>();
    qk_reduce<<<1024, 256>>>(b1);

    scores_kernel<<<dim3(16, 16, 4), 256>>>(v);
    softmax2<<<2048, 256>>>();

    pv_mma_split<<<dim3(8, 8, 16), 128>>>();
    pv_reduce<<<1024, 256>>>(out);
}

// round 11
// speedup vs baseline: 1.4505x; 1.0596x over previous
#include <cuda_runtime.h>
#include <cuda_bf16.h>

#define BB 4
#define SS 512
#define EE 512
#define UU 256

// ---------------- scratch (__device__ globals) ----------------
__device__ float g_K[BB * SS * UU];            // key_pre + b1 (fp32, scores input)
__device__ float g_Q[BB * SS * UU];            // qry_pre
__device__ float g_S[BB * SS * SS];            // raw scores (fp32)
__device__ float g_part[4 * 2048 * 512];       // 16MB split-K partials

// bf16 hi/lo planes, u32 = (bf16 x_{2k+1} << 16) | bf16 x_{2k}
__device__ unsigned g_AH[2 * 2048 * 256];      // h1,h2 row-major [which][row][k-pair]
__device__ unsigned g_AL[2 * 2048 * 256];
__device__ unsigned g_WH[2 * 256 * 256];       // w transposed [which][u][e-pair]
__device__ unsigned g_WL[2 * 256 * 256];
__device__ unsigned g_TH[4 * 512 * 256];       // h1 transposed [b][e][j-pair]
__device__ unsigned g_TL[4 * 512 * 256];
__device__ unsigned g_SH[2048 * 256];          // softmax probs [row][j-pair]
__device__ unsigned g_SL[2048 * 256];

// ---------------- helpers ----------------
__device__ __forceinline__ float tanh_ap(float x) {
    float y; asm("tanh.approx.f32 %0,%1;" : "=f"(y) : "f"(x)); return y;
}
__device__ __forceinline__ float ex2_ap(float x) {
    float y; asm("ex2.approx.f32 %0,%1;" : "=f"(y) : "f"(x)); return y;
}
__device__ __forceinline__ void cp16(void* dst, const void* src) {
    unsigned d = (unsigned)__cvta_generic_to_shared(dst);
    asm volatile("cp.async.ca.shared.global [%0],[%1],16;" :: "r"(d), "l"(src) : "memory");
}
__device__ __forceinline__ void bsplit2(float x0, float x1, unsigned& hi, unsigned& lo) {
    asm("cvt.rn.bf16x2.f32 %0, %1, %2;" : "=r"(hi) : "f"(x1), "f"(x0));
    float b0 = __uint_as_float(hi << 16);
    float b1 = __uint_as_float(hi & 0xffff0000u);
    float l0 = x0 - b0;
    float l1 = x1 - b1;
    asm("cvt.rn.bf16x2.f32 %0, %1, %2;" : "=r"(lo) : "f"(l1), "f"(l0));
}
__device__ __forceinline__ void mma16816(float* c, const unsigned* a,
                                         unsigned b0, unsigned b1) {
    asm volatile(
        "mma.sync.aligned.m16n8k16.row.col.f32.bf16.bf16.f32 "
        "{%0,%1,%2,%3}, {%4,%5,%6,%7}, {%8,%9}, {%0,%1,%2,%3};"
        : "+f"(c[0]), "+f"(c[1]), "+f"(c[2]), "+f"(c[3])
        : "r"(a[0]), "r"(a[1]), "r"(a[2]), "r"(a[3]), "r"(b0), "r"(b1));
}
__device__ __forceinline__ void ldm_x4(unsigned* r, const unsigned* smem_ptr) {
    unsigned a = (unsigned)__cvta_generic_to_shared(smem_ptr);
    asm volatile("ldmatrix.sync.aligned.m8n8.x4.shared.b16 {%0,%1,%2,%3}, [%4];"
                 : "=r"(r[0]), "=r"(r[1]), "=r"(r[2]), "=r"(r[3]) : "r"(a));
}

// ---------------------------------------------------------------------------
// Conversion kernels (unchanged from R10).
// ---------------------------------------------------------------------------
__global__ void __launch_bounds__(256)
conv_rows(const float* __restrict__ h1, const float* __restrict__ h2)
{
    const int i = blockIdx.x * 256 + threadIdx.x;
    float4 v = (i < 262144) ? ((const float4*)h1)[i]
                            : ((const float4*)h2)[i - 262144];
    unsigned h0, l0, h1u, l1u;
    bsplit2(v.x, v.y, h0, l0);
    bsplit2(v.z, v.w, h1u, l1u);
    ((uint2*)g_AH)[i] = make_uint2(h0, h1u);
    ((uint2*)g_AL)[i] = make_uint2(l0, l1u);
}

__global__ void __launch_bounds__(256)
conv_w(const float* __restrict__ w)
{
    __shared__ float tsm[32][33];
    const int tx = threadIdx.x & 31, ty = threadIdx.x >> 5;
    const int c0 = blockIdx.x * 32;
    const int r0 = blockIdx.y * 32;
#pragma unroll
    for (int j = 0; j < 4; j++)
        tsm[ty + 8 * j][tx] = w[(size_t)(r0 + ty + 8 * j) * UU + c0 + tx];
    __syncthreads();
    const int oc = threadIdx.x >> 3;
    const int p  = threadIdx.x & 7;
    const int which = r0 >> 9;
    const int rl = r0 & 511;
    unsigned* oH = g_WH + which * 65536;
    unsigned* oL = g_WL + which * 65536;
    const size_t base = (size_t)(c0 + oc) * 256 + (rl >> 1);
    unsigned h0, l0, h1u, l1u;
    bsplit2(tsm[2 * p][oc],      tsm[2 * p + 1][oc],  h0, l0);
    bsplit2(tsm[2 * p + 16][oc], tsm[2 * p + 17][oc], h1u, l1u);
    oH[base + p] = h0;      oL[base + p] = l0;
    oH[base + p + 8] = h1u; oL[base + p + 8] = l1u;
}

__global__ void __launch_bounds__(256)
conv_h1T(const float* __restrict__ h1)
{
    __shared__ float tsm[32][33];
    const int tx = threadIdx.x & 31, ty = threadIdx.x >> 5;
    const int r0 = blockIdx.x * 32;
    const int c0 = blockIdx.y * 32;
    const int b  = blockIdx.z;
    const float* src = h1 + (size_t)b * SS * EE;
#pragma unroll
    for (int j = 0; j < 4; j++)
        tsm[ty + 8 * j][tx] = src[(size_t)(r0 + ty + 8 * j) * EE + c0 + tx];
    __syncthreads();
    const int oc = threadIdx.x >> 3;
    const int p  = threadIdx.x & 7;
    unsigned* oH = g_TH + (size_t)b * 131072;
    unsigned* oL = g_TL + (size_t)b * 131072;
    const size_t base = (size_t)(c0 + oc) * 256 + (r0 >> 1);
    unsigned h0, l0, h1u, l1u;
    bsplit2(tsm[2 * p][oc],      tsm[2 * p + 1][oc],  h0, l0);
    bsplit2(tsm[2 * p + 16][oc], tsm[2 * p + 17][oc], h1u, l1u);
    oH[base + p] = h0;      oL[base + p] = l0;
    oH[base + p + 8] = h1u; oL[base + p + 8] = l1u;
}

// ---------------------------------------------------------------------------
// 64x64 tile x K=128 chunk GEMM via mma.sync bf16 3x-split.
// 128 threads = 4 warps in a 2(M)x2(N) grid; warp owns m32 x n32.
// Fragments via ldmatrix.x4 (conflict-free thanks to 12-u32 row stride).
// cp.async double-buffered k16 chunks.
// ---------------------------------------------------------------------------
__device__ __forceinline__ void mma_tile(
    const unsigned* __restrict__ AH, const unsigned* __restrict__ AL,
    const unsigned* __restrict__ BH, const unsigned* __restrict__ BL,
    float* __restrict__ P, int ldp, int row0, int col0, int ku0)
{
    __shared__ unsigned sA[2][2][64][12];   // [buf][plane][row][u32], 8 used
    __shared__ unsigned sB[2][2][64][12];

    const int tid = threadIdx.x;
    const int w = tid >> 5, lane = tid & 31;
    const int wm = w >> 1, wn = w & 1;
    const int g = lane >> 2, t = lane & 3;
    const int fr = tid >> 1;              // fill row 0..63
    const int fh = (tid & 1) << 2;        // fill u32 col 0/4

    // ldmatrix source lane mappings
    const int a_row = 32 * wm + (lane & 15);
    const int a_col = (lane & 16) ? 4 : 0;
    const int b_row = 32 * wn + ((lane & 16) ? 8 : 0) + (lane & 7);
    const int b_col = (lane & 8) ? 4 : 0;

    const unsigned* arH = AH + (size_t)(row0 + fr) * 256 + ku0 + fh;
    const unsigned* arL = AL + (size_t)(row0 + fr) * 256 + ku0 + fh;
    const unsigned* brH = BH + (size_t)(col0 + fr) * 256 + ku0 + fh;
    const unsigned* brL = BL + (size_t)(col0 + fr) * 256 + ku0 + fh;

    float acc[2][4][4];
#pragma unroll
    for (int mi = 0; mi < 2; mi++)
#pragma unroll
        for (int nt = 0; nt < 4; nt++)
#pragma unroll
            for (int j = 0; j < 4; j++) acc[mi][nt][j] = 0.f;

    // prefetch chunk 0
    cp16(&sA[0][0][fr][fh], arH);
    cp16(&sA[0][1][fr][fh], arL);
    cp16(&sB[0][0][fr][fh], brH);
    cp16(&sB[0][1][fr][fh], brL);
    asm volatile("cp.async.commit_group;");

#pragma unroll 1
    for (int c = 0; c < 8; c++) {
        const int buf = c & 1;
        asm volatile("cp.async.wait_group 0;");
        __syncthreads();
        if (c < 7) {
            const int nb = buf ^ 1;
            const int off = (c + 1) * 8;
            cp16(&sA[nb][0][fr][fh], arH + off);
            cp16(&sA[nb][1][fr][fh], arL + off);
            cp16(&sB[nb][0][fr][fh], brH + off);
            cp16(&sB[nb][1][fr][fh], brL + off);
            asm volatile("cp.async.commit_group;");
        }

        // fragments: A m32 (2 x m16) x 2 planes, B n32 (2 x n16) x 2 planes
        unsigned aH[2][4], aL[2][4], bH[2][4], bL[2][4];
        ldm_x4(aH[0], &sA[buf][0][a_row][a_col]);
        ldm_x4(aH[1], &sA[buf][0][16 + a_row][a_col]);
        ldm_x4(aL[0], &sA[buf][1][a_row][a_col]);
        ldm_x4(aL[1], &sA[buf][1][16 + a_row][a_col]);
        ldm_x4(bH[0], &sB[buf][0][b_row][b_col]);        // nt 0,1
        ldm_x4(bH[1], &sB[buf][0][16 + b_row][b_col]);   // nt 2,3
        ldm_x4(bL[0], &sB[buf][1][b_row][b_col]);
        ldm_x4(bL[1], &sB[buf][1][16 + b_row][b_col]);

#pragma unroll
        for (int mi = 0; mi < 2; mi++)
#pragma unroll
            for (int h = 0; h < 2; h++)
#pragma unroll
                for (int s = 0; s < 2; s++) {
                    const int nt = 2 * h + s;
                    mma16816(acc[mi][nt], aH[mi], bH[h][2 * s], bH[h][2 * s + 1]);
                    mma16816(acc[mi][nt], aH[mi], bL[h][2 * s], bL[h][2 * s + 1]);
                    mma16816(acc[mi][nt], aL[mi], bH[h][2 * s], bH[h][2 * s + 1]);
                }
    }

#pragma unroll
    for (int mi = 0; mi < 2; mi++) {
        const int orow = row0 + 32 * wm + 16 * mi + g;
#pragma unroll
        for (int nt = 0; nt < 4; nt++) {
            const int ocol = col0 + 32 * wn + 8 * nt + 2 * t;
            *(float2*)&P[(size_t)orow * ldp + ocol] =
                make_float2(acc[mi][nt][0], acc[mi][nt][1]);
            *(float2*)&P[(size_t)(orow + 8) * ldp + ocol] =
                make_float2(acc[mi][nt][2], acc[mi][nt][3]);
        }
    }
}

// Stage 1a: split-K partials, K = h1@w1 (which=0), Q = h2@w2 (which=1).
__global__ void __launch_bounds__(128)
qk_mma_split()
{
    const int which = blockIdx.z >> 2;
    const int ks    = blockIdx.z & 3;
    float* P = g_part + (size_t)(ks * 2 + which) * 2048 * 256;
    mma_tile(g_AH + (size_t)which * 524288, g_AL + (size_t)which * 524288,
             g_WH + which * 65536, g_WL + which * 65536,
             P, 256, blockIdx.y * 64, blockIdx.x * 64, ks * 64);
}

// Stage 1b: reduce partials -> g_K (+b1), g_Q. grid 1024, block 256.
__global__ void __launch_bounds__(256)
qk_reduce(const float* __restrict__ b1)
{
    const int tt = blockIdx.x * 256 + threadIdx.x;
    const int which = tt >> 17;
    const int i4 = tt & 131071;
    const float4* p = (const float4*)g_part + (size_t)which * 131072 + i4;
    float4 s0 = p[0];
    float4 s1 = p[262144];
    float4 s2 = p[524288];
    float4 s3 = p[786432];
    float4 o = make_float4((s0.x + s1.x) + (s2.x + s3.x),
                           (s0.y + s1.y) + (s2.y + s3.y),
                           (s0.z + s1.z) + (s2.z + s3.z),
                           (s0.w + s1.w) + (s2.w + s3.w));
    if (which == 0) {
        const float4 bv = ((const float4*)b1)[i4 & 63];
        o.x += bv.x; o.y += bv.y; o.z += bv.z; o.w += bv.w;
        ((float4*)g_K)[i4] = o;
    } else {
        ((float4*)g_Q)[i4] = o;
    }
}

// Stage 3a: split-K partials for out[b] = P[b] @ h1[b].
__global__ void __launch_bounds__(128)
pv_mma_split()
{
    const int b  = blockIdx.z >> 2;
    const int ks = blockIdx.z & 3;
    float* P = g_part + (size_t)ks * 2048 * 512 + (size_t)b * 512 * 512;
    mma_tile(g_SH + (size_t)b * 131072, g_SL + (size_t)b * 131072,
             g_TH + (size_t)b * 131072, g_TL + (size_t)b * 131072,
             P, 512, blockIdx.y * 64, blockIdx.x * 64, ks * 64);
}

// Stage 3b: reduce partials -> out. grid 1024, block 256.
__global__ void __launch_bounds__(256)
pv_reduce(float* __restrict__ out)
{
    const int i4 = blockIdx.x * 256 + threadIdx.x;
    const float4* p = (const float4*)g_part + i4;
    float4 s0 = p[0];
    float4 s1 = p[262144];
    float4 s2 = p[524288];
    float4 s3 = p[786432];
    ((float4*)out)[i4] = make_float4((s0.x + s1.x) + (s2.x + s3.x),
                                     (s0.y + s1.y) + (s2.y + s3.y),
                                     (s0.z + s1.z) + (s2.z + s3.z),
                                     (s0.w + s1.w) + (s2.w + s3.w));
}

// ---------------------------------------------------------------------------
// Stage 2a: scores (fp32, MUFU-floor bound, unchanged). b2 dropped.
// ---------------------------------------------------------------------------
__global__ void __launch_bounds__(256)
scores_kernel(const float* __restrict__ v)
{
    __shared__ float4 q4[32][32];
    __shared__ float4 k4[32][33];
    __shared__ float4 v4s[32];

    const int b  = blockIdx.z;
    const int it = blockIdx.y;
    const int jt = blockIdx.x;
    const int tid = threadIdx.x;
    const int jl = tid & 31;
    const int ib = tid >> 5;

    const float* Qb = g_Q + ((size_t)(b * SS + it * 32)) * UU;
    const float* Kb = g_K + ((size_t)(b * SS + jt * 32)) * UU;

    float acc[4] = {0.f, 0.f, 0.f, 0.f};

    for (int uc = 0; uc < 2; uc++) {
        const int base = uc * 32;
        for (int tix = tid; tix < 32 * 32; tix += 256) {
            const int r = tix >> 5, c = tix & 31;
            q4[r][c] = ((const float4*)(Qb + (size_t)r * UU))[base + c];
            k4[r][c] = ((const float4*)(Kb + (size_t)r * UU))[base + c];
        }
        if (tid < 32) v4s[tid] = ((const float4*)v)[base + tid];
        __syncthreads();

#pragma unroll 4
        for (int c = 0; c < 32; c++) {
            const float4 kv = k4[jl][c];
            const float4 vv = v4s[c];
#pragma unroll
            for (int r = 0; r < 4; r++) {
                const float4 qv = q4[ib + 8 * r][c];
                acc[r] += vv.x * tanh_ap(qv.x + kv.x);
                acc[r] += vv.y * tanh_ap(qv.y + kv.y);
                acc[r] += vv.z * tanh_ap(qv.z + kv.z);
                acc[r] += vv.w * tanh_ap(qv.w + kv.w);
            }
        }
        __syncthreads();
    }

#pragma unroll
    for (int r = 0; r < 4; r++) {
        const int i = it * 32 + ib + 8 * r;
        g_S[((size_t)(b * SS + i)) * SS + jt * 32 + jl] = acc[r];
    }
}

// Stage 2b: row softmax; emits bf16 hi/lo pair-planes for the pv mma.
__global__ void __launch_bounds__(256)
softmax2()
{
    const int row = blockIdx.x;
    const float* s = g_S + (size_t)row * SS;
    const int tid = threadIdx.x;

    const float2 vv = ((const float2*)s)[tid];
    float m = fmaxf(vv.x, vv.y);
#pragma unroll
    for (int o = 16; o > 0; o >>= 1) m = fmaxf(m, __shfl_xor_sync(0xffffffffu, m, o));
    __shared__ float sm[8];
    __shared__ float ssum[8];
    if ((tid & 31) == 0) sm[tid >> 5] = m;
    __syncthreads();
    float bm = sm[0];
#pragma unroll
    for (int i = 1; i < 8; i++) bm = fmaxf(bm, sm[i]);

    const float L2E = 1.4426950408889634f;
    float e0 = ex2_ap((vv.x - bm) * L2E);
    float e1 = ex2_ap((vv.y - bm) * L2E);
    float su = e0 + e1;
#pragma unroll
    for (int o = 16; o > 0; o >>= 1) su += __shfl_xor_sync(0xffffffffu, su, o);
    if ((tid & 31) == 0) ssum[tid >> 5] = su;
    __syncthreads();
    float bs = 0.f;
#pragma unroll
    for (int i = 0; i < 8; i++) bs += ssum[i];

    const float inv = 1.0f / bs;
    unsigned h, l;
    bsplit2(e0 * inv, e1 * inv, h, l);
    g_SH[(size_t)row * 256 + tid] = h;
    g_SL[(size_t)row * 256 + tid] = l;
}

extern "C" void kernel_launch(void* const* d_in, const int* in_sizes, int n_in,
                              void* d_out, int out_size)
{
    const float* h1 = (const float*)d_in[0];
    const float* h2 = (const float*)d_in[1];
    const float* w  = (const float*)d_in[2];
    const float* b1 = (const float*)d_in[3];
    const float* v  = (const float*)d_in[4];
    // b2 (d_in[5]) unused: softmax is shift-invariant.
    float* out = (float*)d_out;

    conv_rows<<<2048, 256>>>(h1, h2);
    conv_w<<<dim3(8, 32), 256>>>(w);
    conv_h1T<<<dim3(16, 16, 4), 256>>>(h1);

    qk_mma_split<<<dim3(4, 32, 8), 128>>>();
    qk_reduce<<<1024, 256>>>(b1);

    scores_kernel<<<dim3(16, 16, 4), 256>>>(v);
    softmax2<<<2048, 256>>>();

    pv_mma_split<<<dim3(8, 8, 16), 128>>>();
    pv_reduce<<<1024, 256>>>(out);
}